// round 2
// baseline (speedup 1.0000x reference)
#include <cuda_runtime.h>
#include <math.h>

// ============================================================================
// ConvNorm: DoReFa weight-quantized 3x3 conv + BN (inference) + PACT act quant
// Shapes: x[32,256,56,56], w[256,256,3,3], out[32,256,56,56] fp32
// Implicit GEMM: M = C_out = 256, N = B*H*W = 100352, K = C_in*9 = 2304
// ============================================================================

#define C_IN   256
#define C_OUT  256
#define HH     56
#define WW     56
#define BATCH  32
#define KDIM   (C_IN * 9)          // 2304
#define NDIM   (BATCH * HH * WW)   // 100352
#define HWSZ   (HH * WW)           // 3136

// device scratch (no allocations allowed)
__device__ float g_maxt;
__device__ float g_wpack[KDIM * C_OUT];   // [k][co], k = ci*9+kh*3+kw
__device__ float g_scale[C_OUT];
__device__ float g_bias[C_OUT];

// ---------------------------------------------------------------------------
// XLA / Eigen float32 tanh (bit-exact with jnp.tanh on f32):
// clamp to +-7.90531110763549805, rational poly in x^2, |x|<4e-4 -> x
// ---------------------------------------------------------------------------
__device__ __forceinline__ float xla_tanhf(float x) {
    const float kClamp = 7.90531110763549805f;
    float xc = fminf(fmaxf(x, -kClamp), kClamp);
    float x2 = __fmul_rn(xc, xc);
    float p;
    p = __fmaf_rn(x2, -2.76076847742355e-16f, 2.00018790482477e-13f);
    p = __fmaf_rn(x2, p, -8.60467152213735e-11f);
    p = __fmaf_rn(x2, p,  5.12229709037114e-08f);
    p = __fmaf_rn(x2, p,  1.48572235717979e-05f);
    p = __fmaf_rn(x2, p,  6.37261928875436e-04f);
    p = __fmaf_rn(x2, p,  4.89352455891786e-03f);
    p = __fmul_rn(xc, p);
    float q;
    q = __fmaf_rn(x2, 1.19825839466702e-06f, 1.18534705686654e-04f);
    q = __fmaf_rn(x2, q, 2.26843463243900e-03f);
    q = __fmaf_rn(x2, q, 4.89352518554385e-03f);
    float r = __fdiv_rn(p, q);
    return (fabsf(x) < 0.0004f) ? x : r;
}

// ---------------------------------------------------------------------------
__global__ void k_reset() { g_maxt = 0.0f; }

__global__ void k_maxabs(const float* __restrict__ w, int n) {
    float m = 0.0f;
    for (int i = blockIdx.x * blockDim.x + threadIdx.x; i < n;
         i += gridDim.x * blockDim.x)
        m = fmaxf(m, fabsf(xla_tanhf(w[i])));
    #pragma unroll
    for (int o = 16; o; o >>= 1)
        m = fmaxf(m, __shfl_xor_sync(0xFFFFFFFFu, m, o));
    __shared__ float s[32];
    if ((threadIdx.x & 31) == 0) s[threadIdx.x >> 5] = m;
    __syncthreads();
    if (threadIdx.x < 32) {
        m = (threadIdx.x < (blockDim.x >> 5)) ? s[threadIdx.x] : 0.0f;
        #pragma unroll
        for (int o = 16; o; o >>= 1)
            m = fmaxf(m, __shfl_xor_sync(0xFFFFFFFFu, m, o));
        if (threadIdx.x == 0)
            atomicMax((int*)&g_maxt, __float_as_int(m));  // nonneg floats: int order ok
    }
}

// quantize weights exactly like the reference, pack as [k][co]
__global__ void k_pack(const float* __restrict__ w) {
    int idx = blockIdx.x * blockDim.x + threadIdx.x;
    if (idx >= C_OUT * KDIM) return;
    int co  = idx / KDIM;
    int k   = idx - co * KDIM;        // = ci*9 + kh*3 + kw (matches input layout)
    float t = xla_tanhf(w[idx]);
    t = __fadd_rn(__fdiv_rn(t, __fmul_rn(2.0f, g_maxt)), 0.5f);
    float r  = rintf(__fmul_rn(t, 15.0f));            // round half-to-even, like jnp.round
    float tq = __fdiv_rn(r, 15.0f);
    float wq = __fadd_rn(__fmul_rn(2.0f, tq), -1.0f);
    g_wpack[k * C_OUT + co] = wq;
}

// fold BN into per-channel scale/bias
__global__ void k_chan(const float* __restrict__ gamma, const float* __restrict__ beta,
                       const float* __restrict__ mean,  const float* __restrict__ var) {
    int c = threadIdx.x;
    float inv = __fdiv_rn(gamma[c], __fsqrt_rn(__fadd_rn(var[c], 1e-5f)));
    g_scale[c] = inv;
    g_bias[c]  = __fadd_rn(beta[c], -__fmul_rn(mean[c], inv));
}

// ---------------------------------------------------------------------------
// Main conv: 128x128 block tile, BK=8, 256 threads, 8x8 micro-tile
// ---------------------------------------------------------------------------
#define BM 128
#define BN 128
#define BK 8

__global__ __launch_bounds__(256, 2)
void k_conv(const float* __restrict__ x, float* __restrict__ out,
            const float* __restrict__ alpha_p) {
    __shared__ float As[BK][BM];
    __shared__ float Bs[BK][BN];

    const int tid = threadIdx.x;
    const int m0  = blockIdx.y * BM;
    const int n0  = blockIdx.x * BN;

    // loader: 8 rows (k) x 32 threads, 4 consecutive columns each
    const int lr = tid >> 5;
    const int lc = (tid & 31) << 2;

    // compute: 16x16 thread grid, 8x8 outputs each (split 4+4 with +64 offset)
    const int tx = tid & 15;
    const int ty = tid >> 4;

    float acc[8][8];
    #pragma unroll
    for (int i = 0; i < 8; i++)
        #pragma unroll
        for (int j = 0; j < 8; j++) acc[i][j] = 0.0f;

    // per-thread spatial decode for the 4 N-columns it gathers (k-invariant)
    int bL[4], hL[4], wL[4];
    #pragma unroll
    for (int i = 0; i < 4; i++) {
        int n  = n0 + lc + i;
        int b  = n / HWSZ;
        int hw = n - b * HWSZ;
        int h  = hw / WW;
        bL[i] = b; hL[i] = h; wL[i] = hw - h * WW;
    }

    for (int k0 = 0; k0 < KDIM; k0 += BK) {
        const int k  = k0 + lr;
        // A: packed quantized weights (contiguous in m)
        float4 av = *(const float4*)(&g_wpack[k * C_OUT + m0 + lc]);
        // B: gathered shifted input (zero-padded halo)
        int ci = k / 9;
        int r9 = k - ci * 9;
        int kh = r9 / 3;
        int kw = r9 - kh * 3;
        float bv[4];
        #pragma unroll
        for (int i = 0; i < 4; i++) {
            int ih = hL[i] + kh - 1;
            int iw = wL[i] + kw - 1;
            bool ok = ((unsigned)ih < (unsigned)HH) && ((unsigned)iw < (unsigned)WW);
            bv[i] = ok ? __ldg(&x[((bL[i] * C_IN + ci) * HH + ih) * WW + iw]) : 0.0f;
        }

        __syncthreads();
        *(float4*)(&As[lr][lc]) = av;
        *(float4*)(&Bs[lr][lc]) = make_float4(bv[0], bv[1], bv[2], bv[3]);
        __syncthreads();

        #pragma unroll
        for (int kk = 0; kk < BK; kk++) {
            float a[8], bb[8];
            *(float4*)(a)      = *(const float4*)(&As[kk][ty * 4]);
            *(float4*)(a + 4)  = *(const float4*)(&As[kk][64 + ty * 4]);
            *(float4*)(bb)     = *(const float4*)(&Bs[kk][tx * 4]);
            *(float4*)(bb + 4) = *(const float4*)(&Bs[kk][64 + tx * 4]);
            #pragma unroll
            for (int i = 0; i < 8; i++)
                #pragma unroll
                for (int j = 0; j < 8; j++)
                    acc[i][j] = __fmaf_rn(a[i], bb[j], acc[i][j]);
        }
    }

    // epilogue: BN fold + PACT quant (IEEE div to match reference bit-wise)
    const float a_val    = alpha_p[0];
    const float a_over_n = __fdiv_rn(a_val, 15.0f);
    #pragma unroll
    for (int i = 0; i < 8; i++) {
        int m  = m0 + ((i < 4) ? (ty * 4 + i) : (64 + ty * 4 + (i - 4)));
        float sc = g_scale[m];
        float bi = g_bias[m];
        #pragma unroll
        for (int j = 0; j < 8; j++) {
            int n  = n0 + ((j < 4) ? (tx * 4 + j) : (64 + tx * 4 + (j - 4)));
            int b  = n / HWSZ;
            int hw = n - b * HWSZ;
            float y = __fmaf_rn(acc[i][j], sc, bi);
            y = fminf(fmaxf(y, 0.0f), a_val);
            float q = rintf(__fdiv_rn(__fmul_rn(y, 15.0f), a_val));
            out[(b * C_OUT + m) * HWSZ + hw] = __fmul_rn(q, a_over_n);
        }
    }
}

// ---------------------------------------------------------------------------
extern "C" void kernel_launch(void* const* d_in, const int* in_sizes, int n_in,
                              void* d_out, int out_size) {
    const float* x      = (const float*)d_in[0];
    const float* weight = (const float*)d_in[1];
    const float* gamma  = (const float*)d_in[2];
    const float* beta   = (const float*)d_in[3];
    const float* rmean  = (const float*)d_in[4];
    const float* rvar   = (const float*)d_in[5];
    const float* alpha  = (const float*)d_in[6];
    float* out = (float*)d_out;

    const int WELEMS = C_OUT * KDIM;  // 589824

    k_reset<<<1, 1>>>();
    k_maxabs<<<256, 256>>>(weight, WELEMS);
    k_pack<<<(WELEMS + 255) / 256, 256>>>(weight);
    k_chan<<<1, C_OUT>>>(gamma, beta, rmean, rvar);

    dim3 grid(NDIM / BN, C_OUT / BM);   // 784 x 2
    k_conv<<<grid, 256>>>(x, out, alpha);
    (void)in_sizes; (void)n_in; (void)out_size;
}